// round 7
// baseline (speedup 1.0000x reference)
#include <cuda_runtime.h>
#include <cuda.h>
#include <cstdint>

// Rotation 15deg bilinear, border 0. (32,3,512,512) fp32.
// 32x32 dst tile per block, 6 planes/block. Src tile (44x41) fetched by 3D
// TMA (native OOB zero-fill) into a 3-deep smem ring with full/empty
// mbarriers; no __syncthreads in the steady-state loop.
// Per-stage stride padded to a 128B multiple (TMA smem dst alignment req).
// Bilinear from smem: 4 conflict-free LDS + 3 FMA per output.

#define H 512
#define W 512
#define HW (H * W)
#define NPLANES 96

#define TW 32
#define TH 32
#define SW 44             // TMA box width (floats); 176B row pitch (16B mult)
#define SH 41             // TMA box height
#define PITCH SW
#define TILE_FLOATS (SH * PITCH)        // 1804
#define STAGE_FLOATS 1824               // padded: 1824*4 = 7296 = 57*128
#define TILE_BYTES (TILE_FLOATS * 4)    // 7216 (TMA transfer size)
#define NSTAGES 3
#define PP 6
#define PGROUPS (NPLANES / PP)          // 16

#define COS_A 0.96592582628906829f
#define SIN_A 0.25881904510252074f

__device__ __forceinline__ uint32_t smem_u32(const void* p) {
    return (uint32_t)__cvta_generic_to_shared(p);
}
__device__ __forceinline__ void mbar_init(uint32_t mbar, uint32_t count) {
    asm volatile("mbarrier.init.shared.b64 [%0], %1;" :: "r"(mbar), "r"(count) : "memory");
}
__device__ __forceinline__ void mbar_expect_tx(uint32_t mbar, uint32_t bytes) {
    asm volatile("mbarrier.arrive.expect_tx.shared.b64 _, [%0], %1;" :: "r"(mbar), "r"(bytes) : "memory");
}
__device__ __forceinline__ void mbar_arrive(uint32_t mbar) {
    asm volatile("mbarrier.arrive.shared.b64 _, [%0];" :: "r"(mbar) : "memory");
}
__device__ __forceinline__ void mbar_wait_acq(uint32_t mbar, uint32_t parity) {
    asm volatile(
        "{\n\t.reg .pred P;\n\t"
        "WL_%=:\n\t"
        "mbarrier.try_wait.parity.acquire.cta.shared::cta.b64 P, [%0], %1, 0x989680;\n\t"
        "@P bra.uni WD_%=;\n\t"
        "bra.uni WL_%=;\n\t"
        "WD_%=:\n\t}"
        :: "r"(mbar), "r"(parity) : "memory");
}
__device__ __forceinline__ void mbar_wait_rlx(uint32_t mbar, uint32_t parity) {
    asm volatile(
        "{\n\t.reg .pred P;\n\t"
        "WL_%=:\n\t"
        "mbarrier.try_wait.parity.relaxed.cta.shared::cta.b64 P, [%0], %1, 0x989680;\n\t"
        "@P bra.uni WD_%=;\n\t"
        "bra.uni WL_%=;\n\t"
        "WD_%=:\n\t}"
        :: "r"(mbar), "r"(parity) : "memory");
}
__device__ __forceinline__ void tma_load_3d(uint32_t sdst, const CUtensorMap* tmap,
                                            int cx, int cy, int cz, uint32_t mbar) {
    asm volatile(
        "cp.async.bulk.tensor.3d.shared::cta.global.tile.mbarrier::complete_tx::bytes "
        "[%0], [%1, {%2, %3, %4}], [%5];"
        :: "r"(sdst), "l"(tmap), "r"(cx), "r"(cy), "r"(cz), "r"(mbar) : "memory");
}

__global__ __launch_bounds__(256)
void rotation_tma_kernel(const __grid_constant__ CUtensorMap tmap,
                         float* __restrict__ out) {
    __shared__ __align__(128) float tile[NSTAGES][STAGE_FLOATS];   // 21888 B
    __shared__ __align__(8) unsigned long long mbar_full[NSTAGES];
    __shared__ __align__(8) unsigned long long mbar_empty[NSTAGES];

    const int tid  = threadIdx.x;
    const int lane = tid & 31;
    const int wid  = tid >> 5;

    const int tx0 = blockIdx.x * TW;
    const int ty0 = blockIdx.y * TH;
    const int p0  = blockIdx.z * PP;

    // Src bbox. xs min at (tx0, ty0+31); ys min at (tx0, ty0).
    const float xs_min = COS_A * ((float)tx0 - 256.0f)
                       - SIN_A * ((float)(ty0 + TH - 1) - 256.0f) + 256.0f;
    const float ys_min = SIN_A * ((float)tx0 - 256.0f)
                       + COS_A * ((float)ty0 - 256.0f) + 256.0f;
    const int gx0 = ((int)floorf(xs_min) - 1) & ~3;
    const int gy0 = (int)floorf(ys_min) - 1;

    uint32_t mbf[NSTAGES], mbe[NSTAGES], sbuf[NSTAGES];
    #pragma unroll
    for (int s = 0; s < NSTAGES; s++) {
        mbf[s]  = smem_u32(&mbar_full[s]);
        mbe[s]  = smem_u32(&mbar_empty[s]);
        sbuf[s] = smem_u32(&tile[s][0]);
    }

    if (tid == 0) {
        #pragma unroll
        for (int s = 0; s < NSTAGES; s++) {
            mbar_init(mbf[s], 1);
            mbar_init(mbe[s], 256);
        }
    }
    __syncthreads();

    // Prologue: fill first NSTAGES-1 stages.
    if (tid == 0) {
        #pragma unroll
        for (int q = 0; q < NSTAGES - 1; q++) {
            mbar_expect_tx(mbf[q], TILE_BYTES);
            tma_load_3d(sbuf[q], &tmap, gx0, gy0, p0 + q, mbf[q]);
        }
    }

    // Per-thread tap setup (plane-invariant).
    int   offs[4];
    float wxv[4], wyv[4];
    #pragma unroll
    for (int k = 0; k < 4; k++) {
        const int x = tx0 + lane;
        const int y = ty0 + wid + 8 * k;
        const float xf = (float)x - 256.0f;
        const float yf = (float)y - 256.0f;
        const float xs = COS_A * xf - SIN_A * yf + 256.0f;
        const float ys = SIN_A * xf + COS_A * yf + 256.0f;
        const float x0f = floorf(xs);
        const float y0f = floorf(ys);
        wxv[k] = xs - x0f;
        wyv[k] = ys - y0f;
        offs[k] = ((int)y0f - gy0) * PITCH + ((int)x0f - gx0);
    }
    const int obase = (ty0 + wid) * W + (tx0 + lane);
    float* __restrict__ dst0 = out + (long)p0 * HW + obase;

    #pragma unroll
    for (int p = 0; p < PP; p++) {
        // Producer: prefetch plane p+(NSTAGES-1) into its stage (never the
        // stage being consumed now, so no self-wait deadlock).
        if (tid == 0 && p + NSTAGES - 1 < PP) {
            const int q = p + NSTAGES - 1;
            const int s = q % NSTAGES;
            if (q >= NSTAGES)
                mbar_wait_rlx(mbe[s], (q / NSTAGES + 1) & 1);  // prior consumer done
            mbar_expect_tx(mbf[s], TILE_BYTES);
            tma_load_3d(sbuf[s], &tmap, gx0, gy0, p0 + q, mbf[s]);
        }

        const int s = p % NSTAGES;
        mbar_wait_acq(mbf[s], (p / NSTAGES) & 1);

        const float* __restrict__ buf = tile[s];
        float* __restrict__ dst = dst0 + (long)p * HW;

        #pragma unroll
        for (int k = 0; k < 4; k++) {
            const float* t = buf + offs[k];
            const float v00 = t[0];
            const float v01 = t[1];
            const float v10 = t[PITCH];
            const float v11 = t[PITCH + 1];
            const float top = fmaf(wxv[k], v01 - v00, v00);
            const float bot = fmaf(wxv[k], v11 - v10, v10);
            dst[k * (8 * W)] = fmaf(wyv[k], bot - top, top);
        }
        mbar_arrive(mbe[s]);   // release: LDS reads done, stage reusable
    }
}

// ---- host side ----

typedef CUresult (*EncodeTiledFn)(
    CUtensorMap*, CUtensorMapDataType, cuuint32_t, void*,
    const cuuint64_t*, const cuuint64_t*, const cuuint32_t*, const cuuint32_t*,
    CUtensorMapInterleave, CUtensorMapSwizzle, CUtensorMapL2promotion,
    CUtensorMapFloatOOBfill);

extern "C" void kernel_launch(void* const* d_in, const int* in_sizes, int n_in,
                              void* d_out, int out_size) {
    float* in = (float*)d_in[0];
    float* out = (float*)d_out;

    void* fn = nullptr;
    cudaDriverEntryPointQueryResult qres;
    cudaGetDriverEntryPoint("cuTensorMapEncodeTiled", &fn, cudaEnableDefault, &qres);
    EncodeTiledFn encode = (EncodeTiledFn)fn;

    CUtensorMap tmap;
    cuuint64_t gdims[3]    = {W, H, NPLANES};
    cuuint64_t gstrides[2] = {W * sizeof(float), (cuuint64_t)HW * sizeof(float)};
    cuuint32_t box[3]      = {SW, SH, 1};
    cuuint32_t estrides[3] = {1, 1, 1};
    encode(&tmap, CU_TENSOR_MAP_DATA_TYPE_FLOAT32, 3, in,
           gdims, gstrides, box, estrides,
           CU_TENSOR_MAP_INTERLEAVE_NONE, CU_TENSOR_MAP_SWIZZLE_NONE,
           CU_TENSOR_MAP_L2_PROMOTION_L2_128B, CU_TENSOR_MAP_FLOAT_OOB_FILL_NONE);

    dim3 block(256);
    dim3 grid(W / TW, H / TH, PGROUPS);   // 16 x 16 x 16 = 4096
    rotation_tma_kernel<<<grid, block>>>(tmap, out);
}

// round 8
// speedup vs baseline: 1.4132x; 1.4132x over previous
#include <cuda_runtime.h>
#include <cuda.h>
#include <cstdint>

// Rotation 15deg bilinear, border 0. (32,3,512,512) fp32.
// 32x32 dst tile per block, 6 planes/block. Src tile (48x42, the proven
// conflict-free geometry) fetched by 3D TMA (native OOB zero-fill) into a
// 3-deep smem ring with full/empty mbarriers; no __syncthreads in the loop.
// Bilinear from smem: 4 conflict-free LDS + 3 FMA per output.

#define H 512
#define W 512
#define HW (H * W)
#define NPLANES 96

#define TW 32
#define TH 32
#define SW 48             // TMA box width (floats); 192B rows
#define SH 42             // TMA box height
#define PITCH SW
#define TILE_FLOATS (SH * PITCH)        // 2016
#define TILE_BYTES (TILE_FLOATS * 4)    // 8064 = 63*128 (128B-aligned stages)
#define NSTAGES 3
#define PP 6
#define PGROUPS (NPLANES / PP)          // 16

#define COS_A 0.96592582628906829f
#define SIN_A 0.25881904510252074f

__device__ __forceinline__ uint32_t smem_u32(const void* p) {
    return (uint32_t)__cvta_generic_to_shared(p);
}
__device__ __forceinline__ void mbar_init(uint32_t mbar, uint32_t count) {
    asm volatile("mbarrier.init.shared.b64 [%0], %1;" :: "r"(mbar), "r"(count) : "memory");
}
__device__ __forceinline__ void mbar_expect_tx(uint32_t mbar, uint32_t bytes) {
    asm volatile("mbarrier.arrive.expect_tx.shared.b64 _, [%0], %1;" :: "r"(mbar), "r"(bytes) : "memory");
}
__device__ __forceinline__ void mbar_arrive(uint32_t mbar) {
    asm volatile("mbarrier.arrive.shared.b64 _, [%0];" :: "r"(mbar) : "memory");
}
__device__ __forceinline__ void mbar_wait_acq(uint32_t mbar, uint32_t parity) {
    asm volatile(
        "{\n\t.reg .pred P;\n\t"
        "WL_%=:\n\t"
        "mbarrier.try_wait.parity.acquire.cta.shared::cta.b64 P, [%0], %1, 0x989680;\n\t"
        "@P bra.uni WD_%=;\n\t"
        "bra.uni WL_%=;\n\t"
        "WD_%=:\n\t}"
        :: "r"(mbar), "r"(parity) : "memory");
}
__device__ __forceinline__ void mbar_wait_rlx(uint32_t mbar, uint32_t parity) {
    asm volatile(
        "{\n\t.reg .pred P;\n\t"
        "WL_%=:\n\t"
        "mbarrier.try_wait.parity.relaxed.cta.shared::cta.b64 P, [%0], %1, 0x989680;\n\t"
        "@P bra.uni WD_%=;\n\t"
        "bra.uni WL_%=;\n\t"
        "WD_%=:\n\t}"
        :: "r"(mbar), "r"(parity) : "memory");
}
__device__ __forceinline__ void tma_load_3d(uint32_t sdst, const CUtensorMap* tmap,
                                            int cx, int cy, int cz, uint32_t mbar) {
    asm volatile(
        "cp.async.bulk.tensor.3d.shared::cta.global.tile.mbarrier::complete_tx::bytes "
        "[%0], [%1, {%2, %3, %4}], [%5];"
        :: "r"(sdst), "l"(tmap), "r"(cx), "r"(cy), "r"(cz), "r"(mbar) : "memory");
}

__global__ __launch_bounds__(256)
void rotation_tma_kernel(const __grid_constant__ CUtensorMap tmap,
                         float* __restrict__ out) {
    __shared__ __align__(128) float tile[NSTAGES][TILE_FLOATS];   // 24192 B
    __shared__ __align__(8) unsigned long long mbar_full[NSTAGES];
    __shared__ __align__(8) unsigned long long mbar_empty[NSTAGES];

    const int tid  = threadIdx.x;
    const int lane = tid & 31;
    const int wid  = tid >> 5;

    const int tx0 = blockIdx.x * TW;
    const int ty0 = blockIdx.y * TH;
    const int p0  = blockIdx.z * PP;

    // Src bbox. xs min at (tx0, ty0+31); ys min at (tx0, ty0).
    const float xs_min = COS_A * ((float)tx0 - 256.0f)
                       - SIN_A * ((float)(ty0 + TH - 1) - 256.0f) + 256.0f;
    const float ys_min = SIN_A * ((float)tx0 - 256.0f)
                       + COS_A * ((float)ty0 - 256.0f) + 256.0f;
    const int gx0 = ((int)floorf(xs_min) - 1) & ~3;
    const int gy0 = (int)floorf(ys_min) - 1;

    uint32_t mbf[NSTAGES], mbe[NSTAGES], sbuf[NSTAGES];
    #pragma unroll
    for (int s = 0; s < NSTAGES; s++) {
        mbf[s]  = smem_u32(&mbar_full[s]);
        mbe[s]  = smem_u32(&mbar_empty[s]);
        sbuf[s] = smem_u32(&tile[s][0]);
    }

    if (tid == 0) {
        #pragma unroll
        for (int s = 0; s < NSTAGES; s++) {
            mbar_init(mbf[s], 1);
            mbar_init(mbe[s], 256);
        }
    }
    __syncthreads();

    // Prologue: fill first NSTAGES-1 stages.
    if (tid == 0) {
        #pragma unroll
        for (int q = 0; q < NSTAGES - 1; q++) {
            mbar_expect_tx(mbf[q], TILE_BYTES);
            tma_load_3d(sbuf[q], &tmap, gx0, gy0, p0 + q, mbf[q]);
        }
    }

    // Per-thread tap setup (plane-invariant).
    int   offs[4];
    float wxv[4], wyv[4];
    #pragma unroll
    for (int k = 0; k < 4; k++) {
        const int x = tx0 + lane;
        const int y = ty0 + wid + 8 * k;
        const float xf = (float)x - 256.0f;
        const float yf = (float)y - 256.0f;
        const float xs = COS_A * xf - SIN_A * yf + 256.0f;
        const float ys = SIN_A * xf + COS_A * yf + 256.0f;
        const float x0f = floorf(xs);
        const float y0f = floorf(ys);
        wxv[k] = xs - x0f;
        wyv[k] = ys - y0f;
        offs[k] = ((int)y0f - gy0) * PITCH + ((int)x0f - gx0);
    }
    const int obase = (ty0 + wid) * W + (tx0 + lane);
    float* __restrict__ dst0 = out + (long)p0 * HW + obase;

    #pragma unroll
    for (int p = 0; p < PP; p++) {
        // Producer: prefetch plane p+(NSTAGES-1) into its stage (never the
        // stage being consumed now, so no self-wait deadlock).
        if (tid == 0 && p + NSTAGES - 1 < PP) {
            const int q = p + NSTAGES - 1;
            const int s = q % NSTAGES;
            if (q >= NSTAGES)
                mbar_wait_rlx(mbe[s], (q / NSTAGES + 1) & 1);  // prior consumer done
            mbar_expect_tx(mbf[s], TILE_BYTES);
            tma_load_3d(sbuf[s], &tmap, gx0, gy0, p0 + q, mbf[s]);
        }

        const int s = p % NSTAGES;
        mbar_wait_acq(mbf[s], (p / NSTAGES) & 1);

        const float* __restrict__ buf = tile[s];
        float* __restrict__ dst = dst0 + (long)p * HW;

        #pragma unroll
        for (int k = 0; k < 4; k++) {
            const float* t = buf + offs[k];
            const float v00 = t[0];
            const float v01 = t[1];
            const float v10 = t[PITCH];
            const float v11 = t[PITCH + 1];
            const float top = fmaf(wxv[k], v01 - v00, v00);
            const float bot = fmaf(wxv[k], v11 - v10, v10);
            dst[k * (8 * W)] = fmaf(wyv[k], bot - top, top);
        }
        mbar_arrive(mbe[s]);   // release: LDS reads done, stage reusable
    }
}

// ---- host side ----

typedef CUresult (*EncodeTiledFn)(
    CUtensorMap*, CUtensorMapDataType, cuuint32_t, void*,
    const cuuint64_t*, const cuuint64_t*, const cuuint32_t*, const cuuint32_t*,
    CUtensorMapInterleave, CUtensorMapSwizzle, CUtensorMapL2promotion,
    CUtensorMapFloatOOBfill);

extern "C" void kernel_launch(void* const* d_in, const int* in_sizes, int n_in,
                              void* d_out, int out_size) {
    float* in = (float*)d_in[0];
    float* out = (float*)d_out;

    void* fn = nullptr;
    cudaDriverEntryPointQueryResult qres;
    cudaGetDriverEntryPoint("cuTensorMapEncodeTiled", &fn, cudaEnableDefault, &qres);
    EncodeTiledFn encode = (EncodeTiledFn)fn;

    CUtensorMap tmap;
    cuuint64_t gdims[3]    = {W, H, NPLANES};
    cuuint64_t gstrides[2] = {W * sizeof(float), (cuuint64_t)HW * sizeof(float)};
    cuuint32_t box[3]      = {SW, SH, 1};
    cuuint32_t estrides[3] = {1, 1, 1};
    encode(&tmap, CU_TENSOR_MAP_DATA_TYPE_FLOAT32, 3, in,
           gdims, gstrides, box, estrides,
           CU_TENSOR_MAP_INTERLEAVE_NONE, CU_TENSOR_MAP_SWIZZLE_NONE,
           CU_TENSOR_MAP_L2_PROMOTION_L2_128B, CU_TENSOR_MAP_FLOAT_OOB_FILL_NONE);

    dim3 block(256);
    dim3 grid(W / TW, H / TH, PGROUPS);   // 16 x 16 x 16 = 4096
    rotation_tma_kernel<<<grid, block>>>(tmap, out);
}

// round 9
// speedup vs baseline: 1.4751x; 1.0438x over previous
#include <cuda_runtime.h>
#include <cuda.h>
#include <cstdint>

// Rotation 15deg bilinear, border 0. (32,3,512,512) fp32.
// Minimal-pipeline version: 32x32 dst tile, 3 planes/block, 3 smem stages.
// All 3 TMA loads issued in the prologue (stages never reused): no empty
// barriers, no arrives, no producer logic in the loop. 8192 blocks for a
// small wave tail. Bilinear from smem: 4 conflict-free LDS + 3 FMA / output.

#define H 512
#define W 512
#define HW (H * W)
#define NPLANES 96

#define TW 32
#define TH 32
#define SW 48             // TMA box width (floats); 192B rows
#define SH 42             // TMA box height
#define PITCH SW
#define TILE_FLOATS (SH * PITCH)        // 2016
#define TILE_BYTES (TILE_FLOATS * 4)    // 8064 = 63*128 (stages 128B-aligned)
#define NSTAGES 3
#define PP 3
#define PGROUPS (NPLANES / PP)          // 32

#define COS_A 0.96592582628906829f
#define SIN_A 0.25881904510252074f

__device__ __forceinline__ uint32_t smem_u32(const void* p) {
    return (uint32_t)__cvta_generic_to_shared(p);
}
__device__ __forceinline__ void mbar_init(uint32_t mbar, uint32_t count) {
    asm volatile("mbarrier.init.shared.b64 [%0], %1;" :: "r"(mbar), "r"(count) : "memory");
}
__device__ __forceinline__ void mbar_expect_tx(uint32_t mbar, uint32_t bytes) {
    asm volatile("mbarrier.arrive.expect_tx.shared.b64 _, [%0], %1;" :: "r"(mbar), "r"(bytes) : "memory");
}
__device__ __forceinline__ void mbar_wait_acq(uint32_t mbar, uint32_t parity) {
    asm volatile(
        "{\n\t.reg .pred P;\n\t"
        "WL_%=:\n\t"
        "mbarrier.try_wait.parity.acquire.cta.shared::cta.b64 P, [%0], %1, 0x989680;\n\t"
        "@P bra.uni WD_%=;\n\t"
        "bra.uni WL_%=;\n\t"
        "WD_%=:\n\t}"
        :: "r"(mbar), "r"(parity) : "memory");
}
__device__ __forceinline__ void tma_load_3d(uint32_t sdst, const CUtensorMap* tmap,
                                            int cx, int cy, int cz, uint32_t mbar) {
    asm volatile(
        "cp.async.bulk.tensor.3d.shared::cta.global.tile.mbarrier::complete_tx::bytes "
        "[%0], [%1, {%2, %3, %4}], [%5];"
        :: "r"(sdst), "l"(tmap), "r"(cx), "r"(cy), "r"(cz), "r"(mbar) : "memory");
}

__global__ __launch_bounds__(256)
void rotation_tma_kernel(const __grid_constant__ CUtensorMap tmap,
                         float* __restrict__ out) {
    __shared__ __align__(128) float tile[NSTAGES][TILE_FLOATS];   // 24192 B
    __shared__ __align__(8) unsigned long long mbar_full[NSTAGES];

    const int tid  = threadIdx.x;
    const int lane = tid & 31;
    const int wid  = tid >> 5;

    const int tx0 = blockIdx.x * TW;
    const int ty0 = blockIdx.y * TH;
    const int p0  = blockIdx.z * PP;

    // Src bbox. xs min at (tx0, ty0+31); ys min at (tx0, ty0).
    const float xs_min = COS_A * ((float)tx0 - 256.0f)
                       - SIN_A * ((float)(ty0 + TH - 1) - 256.0f) + 256.0f;
    const float ys_min = SIN_A * ((float)tx0 - 256.0f)
                       + COS_A * ((float)ty0 - 256.0f) + 256.0f;
    const int gx0 = ((int)floorf(xs_min) - 1) & ~3;
    const int gy0 = (int)floorf(ys_min) - 1;

    // Prologue: tid 0 inits barriers and issues all 3 plane loads.
    if (tid == 0) {
        #pragma unroll
        for (int s = 0; s < NSTAGES; s++) {
            const uint32_t mb = smem_u32(&mbar_full[s]);
            mbar_init(mb, 1);
            mbar_expect_tx(mb, TILE_BYTES);
            tma_load_3d(smem_u32(&tile[s][0]), &tmap, gx0, gy0, p0 + s, mb);
        }
    }
    __syncthreads();   // barriers initialized before any consumer try_wait

    // Per-thread tap setup (plane-invariant).
    int   offs[4];
    float wxv[4], wyv[4];
    #pragma unroll
    for (int k = 0; k < 4; k++) {
        const int x = tx0 + lane;
        const int y = ty0 + wid + 8 * k;
        const float xf = (float)x - 256.0f;
        const float yf = (float)y - 256.0f;
        const float xs = COS_A * xf - SIN_A * yf + 256.0f;
        const float ys = SIN_A * xf + COS_A * yf + 256.0f;
        const float x0f = floorf(xs);
        const float y0f = floorf(ys);
        wxv[k] = xs - x0f;
        wyv[k] = ys - y0f;
        offs[k] = ((int)y0f - gy0) * PITCH + ((int)x0f - gx0);
    }
    const int obase = (ty0 + wid) * W + (tx0 + lane);
    float* __restrict__ dst0 = out + (long)p0 * HW + obase;

    #pragma unroll
    for (int p = 0; p < PP; p++) {
        mbar_wait_acq(smem_u32(&mbar_full[p]), 0);

        const float* __restrict__ buf = tile[p];
        float* __restrict__ dst = dst0 + (long)p * HW;

        #pragma unroll
        for (int k = 0; k < 4; k++) {
            const float* t = buf + offs[k];
            const float v00 = t[0];
            const float v01 = t[1];
            const float v10 = t[PITCH];
            const float v11 = t[PITCH + 1];
            const float top = fmaf(wxv[k], v01 - v00, v00);
            const float bot = fmaf(wxv[k], v11 - v10, v10);
            dst[k * (8 * W)] = fmaf(wyv[k], bot - top, top);
        }
    }
}

// ---- host side ----

typedef CUresult (*EncodeTiledFn)(
    CUtensorMap*, CUtensorMapDataType, cuuint32_t, void*,
    const cuuint64_t*, const cuuint64_t*, const cuuint32_t*, const cuuint32_t*,
    CUtensorMapInterleave, CUtensorMapSwizzle, CUtensorMapL2promotion,
    CUtensorMapFloatOOBfill);

extern "C" void kernel_launch(void* const* d_in, const int* in_sizes, int n_in,
                              void* d_out, int out_size) {
    float* in = (float*)d_in[0];
    float* out = (float*)d_out;

    void* fn = nullptr;
    cudaDriverEntryPointQueryResult qres;
    cudaGetDriverEntryPoint("cuTensorMapEncodeTiled", &fn, cudaEnableDefault, &qres);
    EncodeTiledFn encode = (EncodeTiledFn)fn;

    CUtensorMap tmap;
    cuuint64_t gdims[3]    = {W, H, NPLANES};
    cuuint64_t gstrides[2] = {W * sizeof(float), (cuuint64_t)HW * sizeof(float)};
    cuuint32_t box[3]      = {SW, SH, 1};
    cuuint32_t estrides[3] = {1, 1, 1};
    encode(&tmap, CU_TENSOR_MAP_DATA_TYPE_FLOAT32, 3, in,
           gdims, gstrides, box, estrides,
           CU_TENSOR_MAP_INTERLEAVE_NONE, CU_TENSOR_MAP_SWIZZLE_NONE,
           CU_TENSOR_MAP_L2_PROMOTION_L2_128B, CU_TENSOR_MAP_FLOAT_OOB_FILL_NONE);

    dim3 block(256);
    dim3 grid(W / TW, H / TH, PGROUPS);   // 16 x 16 x 32 = 8192
    rotation_tma_kernel<<<grid, block>>>(tmap, out);
}

// round 11
// speedup vs baseline: 1.4991x; 1.0163x over previous
#include <cuda_runtime.h>
#include <cuda.h>
#include <cstdint>

// Rotation 15deg bilinear, border 0. (32,3,512,512) fp32.
// R4-champion structure: 32x32 dst tile, 2-stage double-buffered 3D TMA
// (native OOB zero-fill) + one __syncthreads per plane. PP=12 planes/block
// (2048 blocks) to amortize prologues; src box trimmed to 48x41 (proven
// conflict-free pitch 48). Bilinear from smem: 4 LDS + FMAs per output.

#define H 512
#define W 512
#define HW (H * W)
#define NPLANES 96

#define TW 32
#define TH 32
#define SW 48                 // box width (floats); 192B rows; pitch mod 32 = 16
#define SH 41                 // box height (ly_max = 40 exactly fits)
#define PITCH SW
#define TILE_BYTES (SW * SH * 4)     // 7872 (TMA transfer size, 16B mult)
#define STAGE_FLOATS 1984            // 7936B = 62*128 -> both stages 128B-aligned
#define PP 12
#define PGROUPS (NPLANES / PP)       // 8

#define COS_A 0.96592582628906829f
#define SIN_A 0.25881904510252074f

__device__ __forceinline__ uint32_t smem_u32(const void* p) {
    return (uint32_t)__cvta_generic_to_shared(p);
}
__device__ __forceinline__ void mbar_init(uint32_t mbar, uint32_t count) {
    asm volatile("mbarrier.init.shared.b64 [%0], %1;" :: "r"(mbar), "r"(count) : "memory");
}
__device__ __forceinline__ void mbar_expect_tx(uint32_t mbar, uint32_t bytes) {
    asm volatile("mbarrier.arrive.expect_tx.shared.b64 _, [%0], %1;" :: "r"(mbar), "r"(bytes) : "memory");
}
__device__ __forceinline__ void mbar_wait_acq(uint32_t mbar, uint32_t parity) {
    asm volatile(
        "{\n\t.reg .pred P;\n\t"
        "WL_%=:\n\t"
        "mbarrier.try_wait.parity.acquire.cta.shared::cta.b64 P, [%0], %1, 0x989680;\n\t"
        "@P bra.uni WD_%=;\n\t"
        "bra.uni WL_%=;\n\t"
        "WD_%=:\n\t}"
        :: "r"(mbar), "r"(parity) : "memory");
}
__device__ __forceinline__ void tma_load_3d(uint32_t sdst, const CUtensorMap* tmap,
                                            int cx, int cy, int cz, uint32_t mbar) {
    asm volatile(
        "cp.async.bulk.tensor.3d.shared::cta.global.tile.mbarrier::complete_tx::bytes "
        "[%0], [%1, {%2, %3, %4}], [%5];"
        :: "r"(sdst), "l"(tmap), "r"(cx), "r"(cy), "r"(cz), "r"(mbar) : "memory");
}

__global__ __launch_bounds__(256)
void rotation_tma_kernel(const __grid_constant__ CUtensorMap tmap,
                         float* __restrict__ out) {
    __shared__ __align__(128) float tile[2][STAGE_FLOATS];   // 15872 B
    __shared__ __align__(8) unsigned long long mbar_s[2];

    const int tid  = threadIdx.x;
    const int lane = tid & 31;
    const int wid  = tid >> 5;

    const int tx0 = blockIdx.x * TW;
    const int ty0 = blockIdx.y * TH;
    const int p0  = blockIdx.z * PP;

    // Src bbox. xs min at (tx0, ty0+31); ys min at (tx0, ty0).
    const float xs_min = COS_A * ((float)tx0 - 256.0f)
                       - SIN_A * ((float)(ty0 + TH - 1) - 256.0f) + 256.0f;
    const float ys_min = SIN_A * ((float)tx0 - 256.0f)
                       + COS_A * ((float)ty0 - 256.0f) + 256.0f;
    const int gx0 = ((int)floorf(xs_min) - 1) & ~3;   // TMA dim0 coord: keep 16B-aligned
    const int gy0 = (int)floorf(ys_min) - 1;

    const uint32_t mb0 = smem_u32(&mbar_s[0]);
    const uint32_t mb1 = smem_u32(&mbar_s[1]);
    const uint32_t sbuf0 = smem_u32(&tile[0][0]);
    const uint32_t sbuf1 = smem_u32(&tile[1][0]);

    if (tid == 0) {
        mbar_init(mb0, 1);
        mbar_init(mb1, 1);
    }
    __syncthreads();

    // Prefetch plane 0 into buffer 0.
    if (tid == 0) {
        mbar_expect_tx(mb0, TILE_BYTES);
        tma_load_3d(sbuf0, &tmap, gx0, gy0, p0, mb0);
    }

    // Per-thread tap setup (plane-invariant).
    int   offs[4];
    float wxv[4], wyv[4];
    #pragma unroll
    for (int k = 0; k < 4; k++) {
        const int x = tx0 + lane;
        const int y = ty0 + wid + 8 * k;
        const float xf = (float)x - 256.0f;
        const float yf = (float)y - 256.0f;
        const float xs = COS_A * xf - SIN_A * yf + 256.0f;
        const float ys = SIN_A * xf + COS_A * yf + 256.0f;
        const float x0f = floorf(xs);
        const float y0f = floorf(ys);
        wxv[k] = xs - x0f;
        wyv[k] = ys - y0f;
        offs[k] = ((int)y0f - gy0) * PITCH + ((int)x0f - gx0);
    }
    const int obase = (ty0 + wid) * W + (tx0 + lane);
    float* __restrict__ dst0 = out + (long)p0 * HW + obase;

    #pragma unroll
    for (int p = 0; p < PP; p++) {
        // Prefetch next plane into the other buffer (its previous consumer,
        // plane p-1, finished at the __syncthreads ending the last iteration).
        if (p + 1 < PP && tid == 0) {
            const uint32_t mb = ((p + 1) & 1) ? mb1 : mb0;
            const uint32_t sb = ((p + 1) & 1) ? sbuf1 : sbuf0;
            mbar_expect_tx(mb, TILE_BYTES);
            tma_load_3d(sb, &tmap, gx0, gy0, p0 + p + 1, mb);
        }

        // Wait for plane p's tile. Buffer b is used by planes b, b+2, ... ->
        // parity flips every second plane: (p >> 1) & 1.
        mbar_wait_acq((p & 1) ? mb1 : mb0, (p >> 1) & 1);

        const float* __restrict__ buf = tile[p & 1];
        float* __restrict__ dst = dst0 + (long)p * HW;

        #pragma unroll
        for (int k = 0; k < 4; k++) {
            const float* t = buf + offs[k];
            const float v00 = t[0];
            const float v01 = t[1];
            const float v10 = t[PITCH];
            const float v11 = t[PITCH + 1];
            const float top = fmaf(wxv[k], v01 - v00, v00);
            const float bot = fmaf(wxv[k], v11 - v10, v10);
            dst[k * (8 * W)] = fmaf(wyv[k], bot - top, top);
        }
        __syncthreads();   // all reads of buf[p&1] done before it is refilled
    }
}

// ---- host side ----

typedef CUresult (*EncodeTiledFn)(
    CUtensorMap*, CUtensorMapDataType, cuuint32_t, void*,
    const cuuint64_t*, const cuuint64_t*, const cuuint32_t*, const cuuint32_t*,
    CUtensorMapInterleave, CUtensorMapSwizzle, CUtensorMapL2promotion,
    CUtensorMapFloatOOBfill);

extern "C" void kernel_launch(void* const* d_in, const int* in_sizes, int n_in,
                              void* d_out, int out_size) {
    float* in = (float*)d_in[0];
    float* out = (float*)d_out;

    void* fn = nullptr;
    cudaDriverEntryPointQueryResult qres;
    cudaGetDriverEntryPoint("cuTensorMapEncodeTiled", &fn, cudaEnableDefault, &qres);
    EncodeTiledFn encode = (EncodeTiledFn)fn;

    CUtensorMap tmap;
    cuuint64_t gdims[3]    = {W, H, NPLANES};
    cuuint64_t gstrides[2] = {W * sizeof(float), (cuuint64_t)HW * sizeof(float)};
    cuuint32_t box[3]      = {SW, SH, 1};
    cuuint32_t estrides[3] = {1, 1, 1};
    encode(&tmap, CU_TENSOR_MAP_DATA_TYPE_FLOAT32, 3, in,
           gdims, gstrides, box, estrides,
           CU_TENSOR_MAP_INTERLEAVE_NONE, CU_TENSOR_MAP_SWIZZLE_NONE,
           CU_TENSOR_MAP_L2_PROMOTION_L2_128B, CU_TENSOR_MAP_FLOAT_OOB_FILL_NONE);

    dim3 block(256);
    dim3 grid(W / TW, H / TH, PGROUPS);   // 16 x 16 x 8 = 2048
    rotation_tma_kernel<<<grid, block>>>(tmap, out);
}

// round 12
// speedup vs baseline: 1.5160x; 1.0113x over previous
#include <cuda_runtime.h>
#include <cuda.h>
#include <cstdint>

// Rotation 15deg bilinear, border 0. (32,3,512,512) fp32.
// Champion R4 structure (32x32 dst tile, 2-stage double-buffered 3D TMA +
// one __syncthreads per plane, PP=6, 4096 blocks) with PITCH=64:
// bank = lx mod 32 -> the 15deg tap staircase hits ~31 distinct banks,
// eliminating the systematic 2-way LDS conflicts of pitch 48.

#define H 512
#define W 512
#define HW (H * W)
#define NPLANES 96

#define TW 32
#define TH 32
#define SW 64                 // box width (floats); 256B rows; pitch mod 32 = 0
#define SH 41                 // box height (ly_max = 40 exactly fits)
#define PITCH SW
#define TILE_BYTES (SW * SH * 4)     // 10496 = 82*128 (stages 128B-aligned)
#define TILE_FLOATS (SW * SH)
#define PP 6
#define PGROUPS (NPLANES / PP)       // 16

#define COS_A 0.96592582628906829f
#define SIN_A 0.25881904510252074f

__device__ __forceinline__ uint32_t smem_u32(const void* p) {
    return (uint32_t)__cvta_generic_to_shared(p);
}
__device__ __forceinline__ void mbar_init(uint32_t mbar, uint32_t count) {
    asm volatile("mbarrier.init.shared.b64 [%0], %1;" :: "r"(mbar), "r"(count) : "memory");
}
__device__ __forceinline__ void mbar_expect_tx(uint32_t mbar, uint32_t bytes) {
    asm volatile("mbarrier.arrive.expect_tx.shared.b64 _, [%0], %1;" :: "r"(mbar), "r"(bytes) : "memory");
}
__device__ __forceinline__ void mbar_wait_acq(uint32_t mbar, uint32_t parity) {
    asm volatile(
        "{\n\t.reg .pred P;\n\t"
        "WL_%=:\n\t"
        "mbarrier.try_wait.parity.acquire.cta.shared::cta.b64 P, [%0], %1, 0x989680;\n\t"
        "@P bra.uni WD_%=;\n\t"
        "bra.uni WL_%=;\n\t"
        "WD_%=:\n\t}"
        :: "r"(mbar), "r"(parity) : "memory");
}
__device__ __forceinline__ void tma_load_3d(uint32_t sdst, const CUtensorMap* tmap,
                                            int cx, int cy, int cz, uint32_t mbar) {
    asm volatile(
        "cp.async.bulk.tensor.3d.shared::cta.global.tile.mbarrier::complete_tx::bytes "
        "[%0], [%1, {%2, %3, %4}], [%5];"
        :: "r"(sdst), "l"(tmap), "r"(cx), "r"(cy), "r"(cz), "r"(mbar) : "memory");
}

__global__ __launch_bounds__(256)
void rotation_tma_kernel(const __grid_constant__ CUtensorMap tmap,
                         float* __restrict__ out) {
    __shared__ __align__(128) float tile[2][TILE_FLOATS];   // 20992 B
    __shared__ __align__(8) unsigned long long mbar_s[2];

    const int tid  = threadIdx.x;
    const int lane = tid & 31;
    const int wid  = tid >> 5;

    const int tx0 = blockIdx.x * TW;
    const int ty0 = blockIdx.y * TH;
    const int p0  = blockIdx.z * PP;

    // Src bbox. xs min at (tx0, ty0+31); ys min at (tx0, ty0).
    const float xs_min = COS_A * ((float)tx0 - 256.0f)
                       - SIN_A * ((float)(ty0 + TH - 1) - 256.0f) + 256.0f;
    const float ys_min = SIN_A * ((float)tx0 - 256.0f)
                       + COS_A * ((float)ty0 - 256.0f) + 256.0f;
    const int gx0 = ((int)floorf(xs_min) - 1) & ~3;   // TMA dim0 coord: keep 16B-aligned
    const int gy0 = (int)floorf(ys_min) - 1;

    const uint32_t mb0 = smem_u32(&mbar_s[0]);
    const uint32_t mb1 = smem_u32(&mbar_s[1]);
    const uint32_t sbuf0 = smem_u32(&tile[0][0]);
    const uint32_t sbuf1 = smem_u32(&tile[1][0]);

    if (tid == 0) {
        mbar_init(mb0, 1);
        mbar_init(mb1, 1);
    }
    __syncthreads();

    // Prefetch plane 0 into buffer 0.
    if (tid == 0) {
        mbar_expect_tx(mb0, TILE_BYTES);
        tma_load_3d(sbuf0, &tmap, gx0, gy0, p0, mb0);
    }

    // Per-thread tap setup (plane-invariant).
    int   offs[4];
    float wxv[4], wyv[4];
    #pragma unroll
    for (int k = 0; k < 4; k++) {
        const int x = tx0 + lane;
        const int y = ty0 + wid + 8 * k;
        const float xf = (float)x - 256.0f;
        const float yf = (float)y - 256.0f;
        const float xs = COS_A * xf - SIN_A * yf + 256.0f;
        const float ys = SIN_A * xf + COS_A * yf + 256.0f;
        const float x0f = floorf(xs);
        const float y0f = floorf(ys);
        wxv[k] = xs - x0f;
        wyv[k] = ys - y0f;
        offs[k] = ((int)y0f - gy0) * PITCH + ((int)x0f - gx0);
    }
    const int obase = (ty0 + wid) * W + (tx0 + lane);
    float* __restrict__ dst0 = out + (long)p0 * HW + obase;

    #pragma unroll
    for (int p = 0; p < PP; p++) {
        // Prefetch next plane into the other buffer (its previous consumer,
        // plane p-1, finished at the __syncthreads ending the last iteration).
        if (p + 1 < PP && tid == 0) {
            const uint32_t mb = ((p + 1) & 1) ? mb1 : mb0;
            const uint32_t sb = ((p + 1) & 1) ? sbuf1 : sbuf0;
            mbar_expect_tx(mb, TILE_BYTES);
            tma_load_3d(sb, &tmap, gx0, gy0, p0 + p + 1, mb);
        }

        // Wait for plane p's tile. Buffer b serves planes b, b+2, ... ->
        // parity flips every second plane: (p >> 1) & 1.
        mbar_wait_acq((p & 1) ? mb1 : mb0, (p >> 1) & 1);

        const float* __restrict__ buf = tile[p & 1];
        float* __restrict__ dst = dst0 + (long)p * HW;

        #pragma unroll
        for (int k = 0; k < 4; k++) {
            const float* t = buf + offs[k];
            const float v00 = t[0];
            const float v01 = t[1];
            const float v10 = t[PITCH];
            const float v11 = t[PITCH + 1];
            const float top = fmaf(wxv[k], v01 - v00, v00);
            const float bot = fmaf(wxv[k], v11 - v10, v10);
            dst[k * (8 * W)] = fmaf(wyv[k], bot - top, top);
        }
        __syncthreads();   // all reads of buf[p&1] done before it is refilled
    }
}

// ---- host side ----

typedef CUresult (*EncodeTiledFn)(
    CUtensorMap*, CUtensorMapDataType, cuuint32_t, void*,
    const cuuint64_t*, const cuuint64_t*, const cuuint32_t*, const cuuint32_t*,
    CUtensorMapInterleave, CUtensorMapSwizzle, CUtensorMapL2promotion,
    CUtensorMapFloatOOBfill);

extern "C" void kernel_launch(void* const* d_in, const int* in_sizes, int n_in,
                              void* d_out, int out_size) {
    float* in = (float*)d_in[0];
    float* out = (float*)d_out;

    void* fn = nullptr;
    cudaDriverEntryPointQueryResult qres;
    cudaGetDriverEntryPoint("cuTensorMapEncodeTiled", &fn, cudaEnableDefault, &qres);
    EncodeTiledFn encode = (EncodeTiledFn)fn;

    CUtensorMap tmap;
    cuuint64_t gdims[3]    = {W, H, NPLANES};
    cuuint64_t gstrides[2] = {W * sizeof(float), (cuuint64_t)HW * sizeof(float)};
    cuuint32_t box[3]      = {SW, SH, 1};
    cuuint32_t estrides[3] = {1, 1, 1};
    encode(&tmap, CU_TENSOR_MAP_DATA_TYPE_FLOAT32, 3, in,
           gdims, gstrides, box, estrides,
           CU_TENSOR_MAP_INTERLEAVE_NONE, CU_TENSOR_MAP_SWIZZLE_NONE,
           CU_TENSOR_MAP_L2_PROMOTION_L2_128B, CU_TENSOR_MAP_FLOAT_OOB_FILL_NONE);

    dim3 block(256);
    dim3 grid(W / TW, H / TH, PGROUPS);   // 16 x 16 x 16 = 4096
    rotation_tma_kernel<<<grid, block>>>(tmap, out);
}